// round 15
// baseline (speedup 1.0000x reference)
#include <cuda_runtime.h>
#include <cstdint>

// ---------------------------------------------------------------------------
// Fused persistent kernel, ONE launch:
//   Phase 1: precompute scaled/permuted feature rows (2 rows per warp).
//   Grid barrier (512 blocks co-resident by construction).
//   Phase 2: dynamic tile loop over the 1024 64x64 Q tiles.
// Q[n,m] = P[n] + R[m] + sum_h (w2[h]/2)|a+b|, rows pre-scaled by |w|/2,
// h-space sign-partitioned so the inner loop is add2 + add2 (|.|/-|.| folded).
// Replay-safe: barrier/tile counters are monotone (512 and 1536 per run).
// ---------------------------------------------------------------------------

#define NMAX  2048
#define HID   64
#define HP    32
#define GRIDB 512
#define TILES 1024   // (2048/64)^2

__device__ unsigned long long g_aT[HP][NMAX];
__device__ unsigned long long g_bT[HP][NMAX];
__device__ float g_P[NMAX];
__device__ float g_R[NMAX];
__device__ int g_K1;
__device__ int g_mix;
__device__ unsigned g_bar  = 0;   // +512 per run (monotone)
__device__ unsigned g_tile = 0;   // +1536 per run (1024 hits + 512 misses)

__device__ __forceinline__ unsigned long long pack2(float lo, float hi) {
    return (unsigned long long)__float_as_uint(lo) |
           ((unsigned long long)__float_as_uint(hi) << 32);
}

__device__ __forceinline__ int rank_of(int h, unsigned bal0, unsigned bal1,
                                       int pc) {
    bool pos = (h < 32) ? ((bal0 >> h) & 1) : ((bal1 >> (h - 32)) & 1);
    unsigned b0 = pos ? bal0 : ~bal0;
    unsigned b1 = pos ? bal1 : ~bal1;
    int r = (h < 32) ? __popc(b0 & ((1u << h) - 1u))
                     : __popc(b0) + __popc(b1 & ((1u << (h - 32)) - 1u));
    return (pos ? 0 : pc) + r;
}

// ---- packed steps: abs/neg fold into FADD2 operand modifiers --------------
__device__ __forceinline__ void stepP(unsigned long long& acc,
                                      unsigned long long a,
                                      unsigned long long b)
{
    asm("{\n\t.reg .b64 t;\n\t.reg .f32 lo, hi;\n\t"
        "add.rn.f32x2 t, %1, %2;\n\t"
        "mov.b64 {lo, hi}, t;\n\tabs.f32 lo, lo;\n\tabs.f32 hi, hi;\n\t"
        "mov.b64 t, {lo, hi};\n\t"
        "add.rn.f32x2 %0, %0, t;\n\t}"
        : "+l"(acc) : "l"(a), "l"(b));
}
__device__ __forceinline__ void stepN(unsigned long long& acc,
                                      unsigned long long a,
                                      unsigned long long b)
{
    asm("{\n\t.reg .b64 t;\n\t.reg .f32 lo, hi;\n\t"
        "add.rn.f32x2 t, %1, %2;\n\t"
        "mov.b64 {lo, hi}, t;\n\tabs.f32 lo, lo;\n\tabs.f32 hi, hi;\n\t"
        "neg.f32 lo, lo;\n\tneg.f32 hi, hi;\n\t"
        "mov.b64 t, {lo, hi};\n\t"
        "add.rn.f32x2 %0, %0, t;\n\t}"
        : "+l"(acc) : "l"(a), "l"(b));
}
__device__ __forceinline__ void stepM(unsigned long long& acc,
                                      unsigned long long a,
                                      unsigned long long b,
                                      unsigned long long sv)
{
    asm("{\n\t.reg .b64 t;\n\t.reg .f32 lo, hi;\n\t"
        "add.rn.f32x2 t, %1, %2;\n\t"
        "mov.b64 {lo, hi}, t;\n\tabs.f32 lo, lo;\n\tabs.f32 hi, hi;\n\t"
        "mov.b64 t, {lo, hi};\n\t"
        "fma.rn.f32x2 %0, t, %3, %0;\n\t}"
        : "+l"(acc) : "l"(a), "l"(b), "l"(sv));
}

// ---------------------------------------------------------------------------
__global__ void __launch_bounds__(128, 4) fused_kernel(
    const float* __restrict__ job, const float* __restrict__ mac,
    const float* __restrict__ gvec,
    const float* __restrict__ Wj, const float* __restrict__ bj,
    const float* __restrict__ Wm, const float* __restrict__ bm,
    const float* __restrict__ Wg, const float* __restrict__ bg,
    const float* __restrict__ W1, const float* __restrict__ b1,
    const float* __restrict__ W2, const float* __restrict__ b2,
    float* __restrict__ out, int n, int m)
{
    __shared__ __align__(8) float stage[4][64];
    __shared__ unsigned long long sA[HP][64];   // 16 KB
    __shared__ unsigned long long sB[HP][64];   // 16 KB
    __shared__ float sP[64];
    __shared__ float sR[64];
    __shared__ unsigned sBase, sT;

    const int tid  = threadIdx.x;
    const int wrp  = tid >> 5;
    const int lane = tid & 31;

    // ---------------- Phase 1: precompute (2 rows per warp) ----------------
    const float w_lo = W2[lane];
    const float w_hi = W2[lane + 32];
    const unsigned bal0 = __ballot_sync(0xFFFFFFFFu, w_lo >= 0.0f);
    const unsigned bal1 = __ballot_sync(0xFFFFFFFFu, w_hi >= 0.0f);
    const int pc = __popc(bal0) + __popc(bal1);

    if (blockIdx.x == 0 && tid == 0) {
        g_K1  = pc >> 1;
        g_mix = pc & 1;
    }

    const float2 w2p = *(const float2*)&W2[2 * lane];
    const int r0 = rank_of(2 * lane,     bal0, bal1, pc);
    const int r1 = rank_of(2 * lane + 1, bal0, bal1, pc);

    #pragma unroll
    for (int rr = 0; rr < 2; ++rr) {
        const int row = blockIdx.x * 8 + wrp * 2 + rr;
        if (row < n + m) {
            float f0, f1;
            if (row < n) {
                const float x = job[row];
                f0 = 0.0f; f1 = 0.0f;
                #pragma unroll
                for (int j = 0; j < 16; ++j) {
                    float f = fmaxf(fmaf(x, Wj[j], bj[j]), 0.0f);
                    float2 w = *(const float2*)&W1[j * HID + 2 * lane];
                    f0 = fmaf(f, w.x, f0);
                    f1 = fmaf(f, w.y, f1);
                }
            } else {
                const int mm = row - n;
                const float x = mac[mm];
                float2 bb = *(const float2*)&b1[2 * lane];
                f0 = bb.x; f1 = bb.y;
                #pragma unroll
                for (int k = 0; k < 8; ++k) {
                    float gf = bg[k];
                    #pragma unroll
                    for (int i = 0; i < 8; ++i)
                        gf = fmaf(gvec[i], Wg[i * 8 + k], gf);
                    gf = fmaxf(gf, 0.0f);
                    float2 w = *(const float2*)&W1[(32 + k) * HID + 2 * lane];
                    f0 = fmaf(gf, w.x, f0);
                    f1 = fmaf(gf, w.y, f1);
                }
                #pragma unroll
                for (int j = 0; j < 16; ++j) {
                    float f = fmaxf(fmaf(x, Wm[j], bm[j]), 0.0f);
                    float2 w = *(const float2*)&W1[(16 + j) * HID + 2 * lane];
                    f0 = fmaf(f, w.x, f0);
                    f1 = fmaf(f, w.y, f1);
                }
            }
            float s = f0 * (0.5f * w2p.x) + f1 * (0.5f * w2p.y);
            #pragma unroll
            for (int d = 16; d > 0; d >>= 1)
                s += __shfl_xor_sync(0xFFFFFFFFu, s, d);

            stage[wrp][r0] = f0 * (0.5f * fabsf(w2p.x));
            stage[wrp][r1] = f1 * (0.5f * fabsf(w2p.y));
            __syncwarp();
            const float2 v = *(const float2*)&stage[wrp][2 * lane];
            __syncwarp();
            const unsigned long long packed = pack2(v.x, v.y);

            if (row < n) {
                g_aT[lane][row] = packed;
                if (lane == 0) g_P[row] = s + b2[0];
            } else {
                g_bT[lane][row - n] = packed;
                if (lane == 0) g_R[row - n] = s;
            }
        }
    }

    // ---------------- Grid barrier (all 512 blocks co-resident) ------------
    __threadfence();
    __syncthreads();
    if (tid == 0) {
        unsigned old = atomicAdd(&g_bar, 1u);
        unsigned k = old / GRIDB;                 // run index
        unsigned target = (k + 1) * GRIDB;
        while (atomicAdd(&g_bar, 0u) < target) {}
        __threadfence();
        sBase = k * (TILES + GRIDB);              // tile-counter base this run
    }
    __syncthreads();
    const unsigned base = sBase;
    const int K1  = g_K1;
    const int mix = g_mix;

    // ---------------- Phase 2: dynamic tile loop ---------------------------
    const int tx = tid & 15;
    const int ty = tid >> 4;
    const int n0 = ty * 8;
    const int m0 = tx * 4;

    while (true) {
        if (tid == 0) sT = atomicAdd(&g_tile, 1u);
        __syncthreads();
        const unsigned t = sT - base;
        if (t >= TILES) break;

        const int nBase = (int)(t >> 5) * 64;     // 32 tiles per row dim
        const int mBase = (int)(t & 31) * 64;

        if (tid < 64) sP[tid] = g_P[nBase + tid];
        else          sR[tid - 64] = g_R[mBase + (tid - 64)];

        #pragma unroll
        for (int i = 0; i < 16; ++i) {
            int idx = tid + i * 128;
            int h2 = idx >> 6, l = idx & 63;
            sA[h2][l] = g_aT[h2][nBase + l];
            sB[h2][l] = g_bT[h2][mBase + l];
        }
        __syncthreads();

        unsigned long long acc[8][4];
        #pragma unroll
        for (int i = 0; i < 8; ++i)
            #pragma unroll
            for (int j = 0; j < 4; ++j)
                acc[i][j] = 0ull;

        unsigned long long A[8], B[4];

        int h2 = 0;
        #pragma unroll 4
        for (; h2 < K1; ++h2) {
            #pragma unroll
            for (int i = 0; i < 4; ++i) {
                ulonglong2 a = *(const ulonglong2*)&sA[h2][n0 + 2 * i];
                A[2 * i] = a.x; A[2 * i + 1] = a.y;
            }
            #pragma unroll
            for (int j = 0; j < 2; ++j) {
                ulonglong2 b = *(const ulonglong2*)&sB[h2][m0 + 2 * j];
                B[2 * j] = b.x; B[2 * j + 1] = b.y;
            }
            #pragma unroll
            for (int i = 0; i < 8; ++i)
                #pragma unroll
                for (int j = 0; j < 4; ++j)
                    stepP(acc[i][j], A[i], B[j]);
        }

        if (mix) {
            const unsigned long long sv = pack2(1.0f, -1.0f);
            #pragma unroll
            for (int i = 0; i < 4; ++i) {
                ulonglong2 a = *(const ulonglong2*)&sA[h2][n0 + 2 * i];
                A[2 * i] = a.x; A[2 * i + 1] = a.y;
            }
            #pragma unroll
            for (int j = 0; j < 2; ++j) {
                ulonglong2 b = *(const ulonglong2*)&sB[h2][m0 + 2 * j];
                B[2 * j] = b.x; B[2 * j + 1] = b.y;
            }
            #pragma unroll
            for (int i = 0; i < 8; ++i)
                #pragma unroll
                for (int j = 0; j < 4; ++j)
                    stepM(acc[i][j], A[i], B[j], sv);
            ++h2;
        }

        #pragma unroll 4
        for (; h2 < HP; ++h2) {
            #pragma unroll
            for (int i = 0; i < 4; ++i) {
                ulonglong2 a = *(const ulonglong2*)&sA[h2][n0 + 2 * i];
                A[2 * i] = a.x; A[2 * i + 1] = a.y;
            }
            #pragma unroll
            for (int j = 0; j < 2; ++j) {
                ulonglong2 b = *(const ulonglong2*)&sB[h2][m0 + 2 * j];
                B[2 * j] = b.x; B[2 * j + 1] = b.y;
            }
            #pragma unroll
            for (int i = 0; i < 8; ++i)
                #pragma unroll
                for (int j = 0; j < 4; ++j)
                    stepN(acc[i][j], A[i], B[j]);
        }

        // Epilogue: r = acc.lo + acc.hi + P[n] + R[m]
        #pragma unroll
        for (int i = 0; i < 8; ++i) {
            const float pn = sP[n0 + i];
            float r[4];
            #pragma unroll
            for (int j = 0; j < 4; ++j) {
                unsigned long long u = acc[i][j];
                r[j] = (__uint_as_float((unsigned)u) +
                        __uint_as_float((unsigned)(u >> 32))) + (pn + sR[m0 + j]);
            }
            float4 v = make_float4(r[0], r[1], r[2], r[3]);
            *(float4*)&out[(size_t)(nBase + n0 + i) * m + (mBase + m0)] = v;
        }
        __syncthreads();   // protect sA/sB/sP/sR before next tile's fill
    }
}

// ---------------------------------------------------------------------------
// Launch: one persistent kernel.
// ---------------------------------------------------------------------------
extern "C" void kernel_launch(void* const* d_in, const int* in_sizes, int n_in,
                              void* d_out, int out_size)
{
    const float* job  = (const float*)d_in[0];
    const float* mac  = (const float*)d_in[1];
    const float* gvec = (const float*)d_in[2];
    const float* Wj   = (const float*)d_in[3];
    const float* bj   = (const float*)d_in[4];
    const float* Wm   = (const float*)d_in[5];
    const float* bm   = (const float*)d_in[6];
    const float* Wg   = (const float*)d_in[7];
    const float* bg   = (const float*)d_in[8];
    const float* W1   = (const float*)d_in[9];
    const float* b1   = (const float*)d_in[10];
    const float* W2   = (const float*)d_in[11];
    const float* b2   = (const float*)d_in[12];
    float* out = (float*)d_out;

    const int N = in_sizes[0];
    const int M = in_sizes[1];

    fused_kernel<<<GRIDB, 128>>>(job, mac, gvec, Wj, bj, Wm, bm, Wg, bg,
                                 W1, b1, W2, b2, out, N, M);
}